// round 4
// baseline (speedup 1.0000x reference)
#include <cuda_runtime.h>
#include <math.h>

#define CB   8
#define PP   2048
#define DKx  256
#define BB   8192
#define TK   4

// output offsets (elements, fp32)
#define OFF_QV   0ULL
#define OFF_QK   67108864ULL
#define OFF_IND  134217728ULL
#define OFF_DIST 134479872ULL
#define OFF_CNT  134742016ULL
#define OFF_FLAT 135004160ULL

#define NSHORT 8

__device__ int   g_idx[BB * CB * TK];
__device__ int   g_short[BB * CB * NSHORT];
__device__ float g_knorm[CB * PP];

__device__ __forceinline__ float warp_sum(float v) {
    #pragma unroll
    for (int o = 16; o; o >>= 1) v += __shfl_xor_sync(0xffffffffu, v, o);
    return v;
}
__device__ __forceinline__ double warp_sum_d(double v) {
    #pragma unroll
    for (int o = 16; o; o >>= 1) v += __shfl_xor_sync(0xffffffffu, v, o);
    return v;
}

// LayerNorm over 8 rows of 256, one warp per row; fp64 statistics, fp32 output.
__device__ __forceinline__ void ln_rows_d(float (*src)[DKx], float (*dst)[DKx],
                                          const float* __restrict__ g,
                                          const float* __restrict__ b, int tid) {
    int w = tid >> 5, lane = tid & 31;
    float* row = src[w];
    double s = 0.0;
    #pragma unroll
    for (int k = 0; k < 8; k++) s += (double)row[lane + 32 * k];
    s = warp_sum_d(s);
    double mu = s * (1.0 / 256.0);
    double v = 0.0;
    #pragma unroll
    for (int k = 0; k < 8; k++) {
        double t = (double)row[lane + 32 * k] - mu;
        v = fma(t, t, v);
    }
    v = warp_sum_d(v);
    double rs = rsqrt(v * (1.0 / 256.0) + 1e-5);
    #pragma unroll
    for (int k = 0; k < 8; k++) {
        int d = lane + 32 * k;
        dst[w][d] = (float)(((double)row[d] - mu) * rs * (double)g[d] + (double)b[d]);
    }
}

// acc[l] += dot(A_row_l[0:256], wrow[0:256]) for 8 rows, fp64 accumulation.
__device__ __forceinline__ void dot8d(const float* __restrict__ A, int stride,
                                      const float* __restrict__ wrow, double* acc) {
    #pragma unroll 2
    for (int d = 0; d < 256; d += 4) {
        float4 w4 = __ldg((const float4*)(wrow + d));
        double w0 = (double)w4.x, w1 = (double)w4.y,
               w2 = (double)w4.z, w3 = (double)w4.w;
        #pragma unroll
        for (int l = 0; l < 8; l++) {
            float4 a4 = *(const float4*)(A + l * stride + d);
            acc[l] = fma((double)a4.x, w0, acc[l]);
            acc[l] = fma((double)a4.y, w1, acc[l]);
            acc[l] = fma((double)a4.z, w2, acc[l]);
            acc[l] = fma((double)a4.w, w3, acc[l]);
        }
    }
}

// ---------------------------------------------------------------- Kernel A ---
// One block per token index i; fp64-internal, fp32 tensor boundaries.
__global__ void __launch_bounds__(256) enc_kernel(
    const float* __restrict__ x,
    const float* __restrict__ ln1_g, const float* __restrict__ ln1_b,
    const float* __restrict__ w_in,  const float* __restrict__ b_in,
    const float* __restrict__ w_out, const float* __restrict__ b_out,
    const float* __restrict__ ln2_g, const float* __restrict__ ln2_b,
    const float* __restrict__ fw1,   const float* __restrict__ fb1,
    const float* __restrict__ fw2,   const float* __restrict__ fb2,
    const float* __restrict__ dw,    const float* __restrict__ db,
    float* __restrict__ out_flat)
{
    __shared__ __align__(16) float flat_s[8][DKx];   // residual stream (fp32 tensor)
    __shared__ __align__(16) float a_s[8][DKx];      // LN out / attn o
    __shared__ __align__(16) float qkv_s[8][768];    // qkv / ffn hidden
    __shared__ float sc[2][8][8];                    // attention probs

    int i = blockIdx.x, tid = threadIdx.x;

    for (int idx = tid; idx < 2048; idx += 256)
        flat_s[idx >> 8][idx & 255] = x[((size_t)i * 8 + (idx >> 8)) * 256 + (idx & 255)];
    __syncthreads();

    ln_rows_d(flat_s, a_s, ln1_g, ln1_b, tid);
    __syncthreads();

    // qkv = h0 @ w_in^T + b_in  (768 cols, 3 chunks of 256)
    for (int ch = 0; ch < 3; ++ch) {
        int col = ch * 256 + tid;
        double acc[8];
        double bi = (double)b_in[col];
        #pragma unroll
        for (int l = 0; l < 8; l++) acc[l] = bi;
        dot8d(&a_s[0][0], DKx, w_in + (size_t)col * 256, acc);
        #pragma unroll
        for (int l = 0; l < 8; l++) qkv_s[l][col] = (float)acc[l];
    }
    __syncthreads();

    // scores: S[h][l][m] = q_l . k_m / sqrt(128)  (fp64 internal, fp32 out)
    if (tid < 128) {
        int h = tid >> 6, rem = tid & 63, l = rem >> 3, m = rem & 7;
        const float* q  = &qkv_s[l][h * 128];
        const float* kk = &qkv_s[m][256 + h * 128];
        double s = 0.0;
        #pragma unroll 4
        for (int d = 0; d < 128; ++d) s = fma((double)q[d], (double)kk[d], s);
        sc[h][l][m] = (float)(s / 11.313708498984760390566);
    }
    __syncthreads();

    // softmax over m (fp64 internal, fp32 out)
    if (tid < 16) {
        int h = tid >> 3, l = tid & 7;
        float* row = sc[h][l];
        float mx = row[0];
        #pragma unroll
        for (int m = 1; m < 8; m++) mx = fmaxf(mx, row[m]);
        double e[8], sm = 0.0;
        #pragma unroll
        for (int m = 0; m < 8; m++) { e[m] = exp((double)row[m] - (double)mx); sm += e[m]; }
        double inv = 1.0 / sm;
        #pragma unroll
        for (int m = 0; m < 8; m++) row[m] = (float)(e[m] * inv);
    }
    __syncthreads();

    // o[l][e] = sum_m a[h][l][m] * v_m[e], h = e>>7
    {
        int e = tid, h = e >> 7;
        #pragma unroll
        for (int l = 0; l < 8; l++) {
            double s = 0.0;
            #pragma unroll
            for (int m = 0; m < 8; m++)
                s = fma((double)sc[h][l][m], (double)qkv_s[m][512 + e], s);
            a_s[l][e] = (float)s;
        }
    }
    __syncthreads();

    // proj (fp32 round) then fp32 residual add (matches reference op boundary)
    {
        int col = tid;
        double acc[8];
        double bo = (double)b_out[col];
        #pragma unroll
        for (int l = 0; l < 8; l++) acc[l] = bo;
        dot8d(&a_s[0][0], DKx, w_out + (size_t)col * 256, acc);
        #pragma unroll
        for (int l = 0; l < 8; l++) flat_s[l][col] = (float)acc[l] + flat_s[l][col];
    }
    __syncthreads();

    ln_rows_d(flat_s, a_s, ln2_g, ln2_b, tid);
    __syncthreads();

    // ffn1 (fp32 round) + exact gelu in fp64 -> qkv_s[:, 0:256]
    {
        int col = tid;
        double acc[8];
        double b1 = (double)fb1[col];
        #pragma unroll
        for (int l = 0; l < 8; l++) acc[l] = b1;
        dot8d(&a_s[0][0], DKx, fw1 + (size_t)col * 256, acc);
        #pragma unroll
        for (int l = 0; l < 8; l++) {
            double u = (double)(float)acc[l];   // round to fp32 tensor first
            qkv_s[l][col] = (float)(0.5 * u * (1.0 + erf(u * 0.70710678118654752440)));
        }
    }
    __syncthreads();

    // ffn2 (fp32 round) + fp32 residual add
    {
        int col = tid;
        double acc[8];
        double b2 = (double)fb2[col];
        #pragma unroll
        for (int l = 0; l < 8; l++) acc[l] = b2;
        dot8d(&qkv_s[0][0], 768, fw2 + (size_t)col * 256, acc);
        #pragma unroll
        for (int l = 0; l < 8; l++) flat_s[l][col] = (float)acc[l] + flat_s[l][col];
    }
    __syncthreads();

    // dec -> flatten
    {
        int col = tid;
        double acc[8];
        double bd = (double)db[col];
        #pragma unroll
        for (int l = 0; l < 8; l++) acc[l] = bd;
        dot8d(&flat_s[0][0], DKx, dw + (size_t)col * 256, acc);
        #pragma unroll
        for (int l = 0; l < 8; l++)
            out_flat[((size_t)l * BB + i) * 256 + col] = (float)acc[l];
    }
}

// ---------------------------------------------------------------- knorm ------
__global__ void __launch_bounds__(256) knorm_kernel(const float* __restrict__ keys) {
    int gw = (blockIdx.x * 256 + threadIdx.x) >> 5;
    int lane = threadIdx.x & 31;
    if (gw >= CB * PP) return;
    const float* row = keys + (size_t)gw * 256;
    float s = 0.f;
    #pragma unroll
    for (int k = 0; k < 8; k++) { float t = row[lane + 32 * k]; s = fmaf(t, t, s); }
    s = warp_sum(s);
    if (lane == 0) g_knorm[gw] = s;
}

// ---------------------------------------------------------------- Kernel B ---
// Fused distance GEMM + top-8 shortlist per (c,i) row. Block: 16 rows x 2048 cols.
__global__ void __launch_bounds__(256) dist_kernel(
    const float* __restrict__ flat, const float* __restrict__ keys)
{
    __shared__ __align__(16) float F[16][256];
    __shared__ float S[16][257];
    __shared__ float mv[16][128];
    __shared__ unsigned short mi[16][128];

    int c = blockIdx.y, ib = blockIdx.x, tid = threadIdx.x;
    int i0 = ib * 16;
    int r = tid & 15, sub = tid >> 4;

    for (int idx = tid; idx < 4096; idx += 256) {
        int rr = idx >> 8, d = idx & 255;
        F[rr][d] = flat[((size_t)c * BB + i0 + rr) * 256 + d];
    }
    __syncthreads();

    float tv[NSHORT];
    int   ti[NSHORT];
    #pragma unroll
    for (int t = 0; t < NSHORT; ++t) { tv[t] = -1e30f; ti[t] = 0; }

    for (int tile = 0; tile < 8; ++tile) {
        int j = tile * 256 + tid;
        const float* krow = keys + ((size_t)c * PP + j) * 256;
        float kn = g_knorm[c * PP + j];
        #pragma unroll
        for (int rc = 0; rc < 2; ++rc) {
            float acc[8] = {0.f, 0.f, 0.f, 0.f, 0.f, 0.f, 0.f, 0.f};
            #pragma unroll 4
            for (int d = 0; d < 256; d += 4) {
                float4 k4 = __ldg((const float4*)(krow + d));
                #pragma unroll
                for (int rr = 0; rr < 8; ++rr) {
                    float4 f4 = *(const float4*)(&F[rc * 8 + rr][d]);
                    acc[rr] = fmaf(f4.x, k4.x, acc[rr]);
                    acc[rr] = fmaf(f4.y, k4.y, acc[rr]);
                    acc[rr] = fmaf(f4.z, k4.z, acc[rr]);
                    acc[rr] = fmaf(f4.w, k4.w, acc[rr]);
                }
            }
            #pragma unroll
            for (int rr = 0; rr < 8; ++rr)
                S[rc * 8 + rr][tid] = fmaf(2.f, acc[rr], -kn);
        }
        __syncthreads();
        // parallel top-8: each thread scans 16 columns of its row
        #pragma unroll 4
        for (int q = 0; q < 16; ++q) {
            int col = sub * 16 + q;
            float v = S[r][col];
            int jj = tile * 256 + col;
            if (v > tv[NSHORT - 1]) {
                tv[NSHORT - 1] = v; ti[NSHORT - 1] = jj;
                #pragma unroll
                for (int p = NSHORT - 1; p > 0; --p) {
                    if (tv[p] > tv[p - 1] || (tv[p] == tv[p - 1] && ti[p] < ti[p - 1])) {
                        float a = tv[p]; tv[p] = tv[p - 1]; tv[p - 1] = a;
                        int   b = ti[p]; ti[p] = ti[p - 1]; ti[p - 1] = b;
                    }
                }
            }
        }
        __syncthreads();
    }

    // merge 16 per-thread lists per row
    #pragma unroll
    for (int t = 0; t < NSHORT; ++t) {
        mv[r][sub * 8 + t] = tv[t];
        mi[r][sub * 8 + t] = (unsigned short)ti[t];
    }
    __syncthreads();

    if (tid < 16) {
        int row = tid;
        float fv[NSHORT];
        int   fi[NSHORT];
        #pragma unroll
        for (int t = 0; t < NSHORT; ++t) { fv[t] = -1e30f; fi[t] = 0; }
        for (int e = 0; e < 128; ++e) {
            float v = mv[row][e];
            int jj = (int)mi[row][e];
            if (v > fv[NSHORT - 1] || (v == fv[NSHORT - 1] && jj < fi[NSHORT - 1])) {
                fv[NSHORT - 1] = v; fi[NSHORT - 1] = jj;
                #pragma unroll
                for (int p = NSHORT - 1; p > 0; --p) {
                    if (fv[p] > fv[p - 1] || (fv[p] == fv[p - 1] && fi[p] < fi[p - 1])) {
                        float a = fv[p]; fv[p] = fv[p - 1]; fv[p - 1] = a;
                        int   b = fi[p]; fi[p] = fi[p - 1]; fi[p - 1] = b;
                    }
                }
            }
        }
        int ig = i0 + row;
        #pragma unroll
        for (int t = 0; t < NSHORT; ++t)
            g_short[((size_t)ig * 8 + c) * NSHORT + t] = fi[t];
    }
}

// ---------------------------------------------------------------- refine -----
// Emulate the reference's fp32 dist values: A=|f|^2, B=2*(f.k), C=|k|^2 computed
// exactly (fp64) then rounded to fp32 at the reference's tensor boundaries, and
// combined with the reference's elementwise fp32 expression -(A - B + C).
// Rank by (dist32 desc, index asc) — matching jax.lax.top_k's stable tie-break.
__global__ void __launch_bounds__(256) refine_kernel(
    const float* __restrict__ flat, const float* __restrict__ keys,
    const float* __restrict__ counter, float* __restrict__ out)
{
    int gw = (blockIdx.x * 256 + threadIdx.x) >> 5;   // row = i*8 + c
    int lane = threadIdx.x & 31;
    if (gw >= BB * CB) return;
    int i = gw >> 3, c = gw & 7;

    const float* frow = flat + ((size_t)c * BB + i) * 256;
    double f[8];
    double fn = 0.0;
    #pragma unroll
    for (int k = 0; k < 8; k++) {
        f[k] = (double)frow[lane + 32 * k];
        fn += f[k] * f[k];
    }
    fn = warp_sum_d(fn);

    float sv[NSHORT];
    int   si[NSHORT];
    float A32 = (float)fn;                       // reference's f2 tensor (fp32)
    #pragma unroll
    for (int t = 0; t < NSHORT; ++t) {
        int idx = g_short[(size_t)gw * NSHORT + t];
        si[t] = idx;
        const float* krow = keys + ((size_t)c * PP + idx) * 256;
        double dot = 0.0, kn = 0.0;
        #pragma unroll
        for (int k = 0; k < 8; k++) {
            double kd = (double)krow[lane + 32 * k];
            dot += f[k] * kd;
            kn  += kd * kd;
        }
        dot = warp_sum_d(dot);
        kn  = warp_sum_d(kn);
        // fp32 boundary emulation: einsum -> fp32, *2 exact; k2 -> fp32;
        // then (A - B) + C in fp32, negate.
        float B32 = 2.0f * (float)dot;
        float C32 = (float)kn;
        float t1  = __fadd_rn(A32, -B32);
        float t2  = __fadd_rn(t1, C32);
        sv[t] = -t2;
    }

    if (lane == 0) {
        // top-4 over emulated fp32 dist, tie-break: lower index first
        #pragma unroll
        for (int a = 0; a < TK; ++a) {
            int best = a;
            #pragma unroll
            for (int b2 = a + 1; b2 < NSHORT; ++b2) {
                if (sv[b2] > sv[best] || (sv[b2] == sv[best] && si[b2] < si[best]))
                    best = b2;
            }
            float vtmp = sv[a]; sv[a] = sv[best]; sv[best] = vtmp;
            int   itmp = si[a]; si[a] = si[best]; si[best] = itmp;
            size_t o = ((size_t)i * 8 + c) * 4 + a;
            out[OFF_IND + o]  = (float)si[a];
            out[OFF_DIST + o] = sv[a];
            out[OFF_CNT + o]  = counter[c * PP + si[a]];
            g_idx[o] = si[a];
        }
    }
}

// ---------------------------------------------------------------- Kernel C ---
// Gather qk/qv rows: one warp per (i,c,t) row, 256 floats each.
__global__ void __launch_bounds__(256) gather_kernel(
    const float* __restrict__ keys, const float* __restrict__ values,
    float* __restrict__ out)
{
    int gw = (blockIdx.x * 256 + threadIdx.x) >> 5;
    int lane = threadIdx.x & 31;
    int c = (gw >> 2) & 7;
    int idx = g_idx[gw];
    const float4* ks = (const float4*)(keys   + ((size_t)c * PP + idx) * 256);
    const float4* vs = (const float4*)(values + ((size_t)c * PP + idx) * 256);
    float4* oqk = (float4*)(out + OFF_QK) + (size_t)gw * 64;
    float4* oqv = (float4*)(out + OFF_QV) + (size_t)gw * 64;
    oqv[lane]      = vs[lane];
    oqv[lane + 32] = vs[lane + 32];
    oqk[lane]      = ks[lane];
    oqk[lane + 32] = ks[lane + 32];
}

// -----------------------------------------------------------------------------
extern "C" void kernel_launch(void* const* d_in, const int* in_sizes, int n_in,
                              void* d_out, int out_size) {
    const float* x       = (const float*)d_in[0];
    const float* keys    = (const float*)d_in[1];
    const float* values  = (const float*)d_in[2];
    const float* counter = (const float*)d_in[3];
    const float* ln1_g   = (const float*)d_in[4];
    const float* ln1_b   = (const float*)d_in[5];
    const float* w_in    = (const float*)d_in[6];
    const float* b_in    = (const float*)d_in[7];
    const float* w_out   = (const float*)d_in[8];
    const float* b_out   = (const float*)d_in[9];
    const float* ln2_g   = (const float*)d_in[10];
    const float* ln2_b   = (const float*)d_in[11];
    const float* fw1     = (const float*)d_in[12];
    const float* fb1     = (const float*)d_in[13];
    const float* fw2     = (const float*)d_in[14];
    const float* fb2     = (const float*)d_in[15];
    const float* dw      = (const float*)d_in[16];
    const float* db      = (const float*)d_in[17];
    float* out = (float*)d_out;

    knorm_kernel<<<2048, 256>>>(keys);
    enc_kernel<<<BB, 256>>>(x, ln1_g, ln1_b, w_in, b_in, w_out, b_out,
                            ln2_g, ln2_b, fw1, fb1, fw2, fb2, dw, db,
                            out + OFF_FLAT);
    dist_kernel<<<dim3(BB / 16, CB), 256>>>(out + OFF_FLAT, keys);
    refine_kernel<<<BB * CB / 8, 256>>>(out + OFF_FLAT, keys, counter, out);
    gather_kernel<<<32768, 256>>>(keys, values, out);
}

// round 5
// speedup vs baseline: 18.1612x; 18.1612x over previous
#include <cuda_runtime.h>
#include <math.h>

#define CB   8
#define PP   2048
#define DKx  256
#define BB   8192
#define TK   4

// output offsets (elements, fp32)
#define OFF_QV   0ULL
#define OFF_QK   67108864ULL
#define OFF_IND  134217728ULL
#define OFF_DIST 134479872ULL
#define OFF_CNT  134742016ULL
#define OFF_FLAT 135004160ULL

#define NSHORT 8

__device__ int    g_idx[BB * CB * TK];
__device__ int    g_short[BB * CB * NSHORT];
__device__ float  g_knorm[CB * PP];
// transposed operands: coalesced loads (float4 over the contraction dim)
__device__ float4 g_kT[CB * 64 * PP];      // [(c*64 + d4)*2048 + j]
__device__ float4 g_wT_in[64 * 768];       // [d4*768 + col]
__device__ float4 g_wT_out[64 * 256];
__device__ float4 g_wT_f1[64 * 256];
__device__ float4 g_wT_f2[64 * 256];
__device__ float4 g_wT_dec[64 * 256];

__device__ __forceinline__ float warp_sum(float v) {
    #pragma unroll
    for (int o = 16; o; o >>= 1) v += __shfl_xor_sync(0xffffffffu, v, o);
    return v;
}
__device__ __forceinline__ double warp_sum_d(double v) {
    #pragma unroll
    for (int o = 16; o; o >>= 1) v += __shfl_xor_sync(0xffffffffu, v, o);
    return v;
}

// Kahan compensated add (intrinsics defeat contraction/reassociation)
__device__ __forceinline__ void kadd(float& s, float& c, float v) {
    float y = __fsub_rn(v, c);
    float t = __fadd_rn(s, y);
    c = __fsub_rn(__fsub_rn(t, s), y);
    s = t;
}

// ------------------------------------------------------------- transposes ---
__global__ void __launch_bounds__(256) transW_kernel(
    const float* __restrict__ src, float4* __restrict__ dst, int NC) {
    int idx = blockIdx.x * 256 + threadIdx.x;           // idx = d4*NC + col
    if (idx >= 64 * NC) return;
    int d4 = idx / NC, col = idx % NC;
    const float* p = src + (size_t)col * 256 + 4 * d4;
    dst[idx] = make_float4(p[0], p[1], p[2], p[3]);
}

__global__ void __launch_bounds__(256) transK_kernel(const float* __restrict__ keys) {
    int idx = blockIdx.x * 256 + threadIdx.x;           // ((c*64+d4)*2048 + j)
    int j = idx & 2047, rest = idx >> 11;
    int d4 = rest & 63, c = rest >> 6;
    const float* p = keys + ((size_t)c * PP + j) * 256 + 4 * d4;
    g_kT[idx] = make_float4(p[0], p[1], p[2], p[3]);
}

// ----------------------------------------------------------------- LN -------
__device__ __forceinline__ void ln_rows(float (*src)[DKx], float (*dst)[DKx],
                                        const float* __restrict__ g,
                                        const float* __restrict__ b, int tid) {
    int w = tid >> 5, lane = tid & 31;
    float* row = src[w];
    float s = 0.f;
    #pragma unroll
    for (int k = 0; k < 8; k++) s += row[lane + 32 * k];
    s = warp_sum(s);
    float mu = s * (1.f / 256.f);
    float v = 0.f;
    #pragma unroll
    for (int k = 0; k < 8; k++) { float t = row[lane + 32 * k] - mu; v = fmaf(t, t, v); }
    v = warp_sum(v);
    float rs = 1.0f / sqrtf(v * (1.f / 256.f) + 1e-5f);
    #pragma unroll
    for (int k = 0; k < 8; k++) {
        int d = lane + 32 * k;
        dst[w][d] = (row[d] - mu) * rs * g[d] + b[d];
    }
}

// Compensated 8-row dot: A (shared, broadcast), wT4 coalesced by col.
__device__ __forceinline__ void dot8k(const float4* __restrict__ A4, int stride4,
                                      const float4* __restrict__ wT4, int NC, int col,
                                      float* out) {
    float s[8], c[8];
    #pragma unroll
    for (int l = 0; l < 8; l++) { s[l] = 0.f; c[l] = 0.f; }
    #pragma unroll 4
    for (int d4 = 0; d4 < 64; ++d4) {
        float4 w = __ldg(wT4 + (size_t)d4 * NC + col);
        #pragma unroll
        for (int l = 0; l < 8; l++) {
            float4 a = A4[l * stride4 + d4];
            float ch = a.x * w.x;
            ch = fmaf(a.y, w.y, ch);
            ch = fmaf(a.z, w.z, ch);
            ch = fmaf(a.w, w.w, ch);
            kadd(s[l], c[l], ch);
        }
    }
    #pragma unroll
    for (int l = 0; l < 8; l++) out[l] = __fadd_rn(s[l], c[l]);
}

// ---------------------------------------------------------------- Kernel A ---
__global__ void __launch_bounds__(256) enc_kernel(
    const float* __restrict__ x,
    const float* __restrict__ ln1_g, const float* __restrict__ ln1_b,
    const float* __restrict__ b_in,  const float* __restrict__ b_out,
    const float* __restrict__ ln2_g, const float* __restrict__ ln2_b,
    const float* __restrict__ fb1,   const float* __restrict__ fb2,
    const float* __restrict__ db,
    float* __restrict__ out_flat)
{
    __shared__ __align__(16) float flat_s[8][DKx];
    __shared__ __align__(16) float a_s[8][DKx];
    __shared__ __align__(16) float qkv_s[8][768];
    __shared__ float sc[2][8][8];

    int i = blockIdx.x, tid = threadIdx.x;

    for (int idx = tid; idx < 2048; idx += 256)
        flat_s[idx >> 8][idx & 255] = x[((size_t)i * 8 + (idx >> 8)) * 256 + (idx & 255)];
    __syncthreads();

    ln_rows(flat_s, a_s, ln1_g, ln1_b, tid);
    __syncthreads();

    // qkv = h0 @ w_in^T + b_in
    for (int ch = 0; ch < 3; ++ch) {
        int col = ch * 256 + tid;
        float res[8];
        dot8k((const float4*)&a_s[0][0], 64, g_wT_in, 768, col, res);
        float bi = b_in[col];
        #pragma unroll
        for (int l = 0; l < 8; l++) qkv_s[l][col] = __fadd_rn(res[l], bi);
    }
    __syncthreads();

    // scores (fp32, 4-way split accumulators)
    if (tid < 128) {
        int h = tid >> 6, rem = tid & 63, l = rem >> 3, m = rem & 7;
        const float* q  = &qkv_s[l][h * 128];
        const float* kk = &qkv_s[m][256 + h * 128];
        float a0 = 0.f, a1 = 0.f, a2 = 0.f, a3 = 0.f;
        #pragma unroll 8
        for (int d = 0; d < 128; d += 4) {
            a0 = fmaf(q[d],     kk[d],     a0);
            a1 = fmaf(q[d + 1], kk[d + 1], a1);
            a2 = fmaf(q[d + 2], kk[d + 2], a2);
            a3 = fmaf(q[d + 3], kk[d + 3], a3);
        }
        float s = __fadd_rn(__fadd_rn(a0, a1), __fadd_rn(a2, a3));
        sc[h][l][m] = s / 11.313708498984760f;
    }
    __syncthreads();

    // softmax
    if (tid < 16) {
        int h = tid >> 3, l = tid & 7;
        float* row = sc[h][l];
        float mx = row[0];
        #pragma unroll
        for (int m = 1; m < 8; m++) mx = fmaxf(mx, row[m]);
        float e[8], sm = 0.f;
        #pragma unroll
        for (int m = 0; m < 8; m++) { e[m] = expf(row[m] - mx); sm += e[m]; }
        float inv = 1.f / sm;
        #pragma unroll
        for (int m = 0; m < 8; m++) row[m] = e[m] * inv;
    }
    __syncthreads();

    // o = a @ v
    {
        int e = tid, h = e >> 7;
        #pragma unroll
        for (int l = 0; l < 8; l++) {
            float s = 0.f;
            #pragma unroll
            for (int m = 0; m < 8; m++) s = fmaf(sc[h][l][m], qkv_s[m][512 + e], s);
            a_s[l][e] = s;
        }
    }
    __syncthreads();

    // proj + residual
    {
        int col = tid;
        float res[8];
        dot8k((const float4*)&a_s[0][0], 64, g_wT_out, 256, col, res);
        float bo = b_out[col];
        #pragma unroll
        for (int l = 0; l < 8; l++)
            flat_s[l][col] = __fadd_rn(__fadd_rn(res[l], bo), flat_s[l][col]);
    }
    __syncthreads();

    ln_rows(flat_s, a_s, ln2_g, ln2_b, tid);
    __syncthreads();

    // ffn1 + gelu (exact, fp32 erff)
    {
        int col = tid;
        float res[8];
        dot8k((const float4*)&a_s[0][0], 64, g_wT_f1, 256, col, res);
        float b1 = fb1[col];
        #pragma unroll
        for (int l = 0; l < 8; l++) {
            float u = __fadd_rn(res[l], b1);
            qkv_s[l][col] = 0.5f * u * (1.0f + erff(u * 0.70710678118654752f));
        }
    }
    __syncthreads();

    // ffn2 + residual
    {
        int col = tid;
        float res[8];
        dot8k((const float4*)&qkv_s[0][0], 192, g_wT_f2, 256, col, res);
        float b2 = fb2[col];
        #pragma unroll
        for (int l = 0; l < 8; l++)
            flat_s[l][col] = __fadd_rn(__fadd_rn(res[l], b2), flat_s[l][col]);
    }
    __syncthreads();

    // dec -> flatten
    {
        int col = tid;
        float res[8];
        dot8k((const float4*)&flat_s[0][0], 64, g_wT_dec, 256, col, res);
        float bd = db[col];
        #pragma unroll
        for (int l = 0; l < 8; l++)
            out_flat[((size_t)l * BB + i) * 256 + col] = __fadd_rn(res[l], bd);
    }
}

// ---------------------------------------------------------------- knorm ------
__global__ void __launch_bounds__(256) knorm_kernel(const float* __restrict__ keys) {
    int gw = (blockIdx.x * 256 + threadIdx.x) >> 5;
    int lane = threadIdx.x & 31;
    if (gw >= CB * PP) return;
    const float* row = keys + (size_t)gw * 256;
    float s = 0.f;
    #pragma unroll
    for (int k = 0; k < 8; k++) { float t = row[lane + 32 * k]; s = fmaf(t, t, s); }
    s = warp_sum(s);
    if (lane == 0) g_knorm[gw] = s;
}

// ---------------------------------------------------------------- Kernel B ---
// Fused distance GEMM + top-8 shortlist; keys read coalesced from g_kT.
__global__ void __launch_bounds__(256) dist_kernel(const float* __restrict__ flat)
{
    __shared__ __align__(16) float F[16][256];
    __shared__ float S[16][257];
    __shared__ float mv[16][128];
    __shared__ unsigned short mi[16][128];

    int c = blockIdx.y, ib = blockIdx.x, tid = threadIdx.x;
    int i0 = ib * 16;
    int r = tid & 15, sub = tid >> 4;

    for (int idx = tid; idx < 4096; idx += 256) {
        int rr = idx >> 8, d = idx & 255;
        F[rr][d] = flat[((size_t)c * BB + i0 + rr) * 256 + d];
    }
    __syncthreads();

    float tv[NSHORT];
    int   ti[NSHORT];
    #pragma unroll
    for (int t = 0; t < NSHORT; ++t) { tv[t] = -1e30f; ti[t] = 0; }

    const float4* F4 = (const float4*)&F[0][0];

    for (int tile = 0; tile < 8; ++tile) {
        int j = tile * 256 + tid;
        const float4* kp = g_kT + (size_t)c * 64 * PP + j;
        float acc[16];
        #pragma unroll
        for (int rr = 0; rr < 16; ++rr) acc[rr] = 0.f;
        #pragma unroll 2
        for (int d4 = 0; d4 < 64; ++d4) {
            float4 k4 = __ldg(kp + (size_t)d4 * PP);
            #pragma unroll
            for (int rr = 0; rr < 16; ++rr) {
                float4 f4 = F4[rr * 64 + d4];
                acc[rr] = fmaf(f4.x, k4.x, acc[rr]);
                acc[rr] = fmaf(f4.y, k4.y, acc[rr]);
                acc[rr] = fmaf(f4.z, k4.z, acc[rr]);
                acc[rr] = fmaf(f4.w, k4.w, acc[rr]);
            }
        }
        float kn = g_knorm[c * PP + j];
        #pragma unroll
        for (int rr = 0; rr < 16; ++rr)
            S[rr][tid] = fmaf(2.f, acc[rr], -kn);
        __syncthreads();
        // parallel top-8: each thread scans 16 columns of its row
        #pragma unroll 4
        for (int q = 0; q < 16; ++q) {
            int col = sub * 16 + q;
            float v = S[r][col];
            int jj = tile * 256 + col;
            if (v > tv[NSHORT - 1]) {
                tv[NSHORT - 1] = v; ti[NSHORT - 1] = jj;
                #pragma unroll
                for (int p = NSHORT - 1; p > 0; --p) {
                    if (tv[p] > tv[p - 1] || (tv[p] == tv[p - 1] && ti[p] < ti[p - 1])) {
                        float a = tv[p]; tv[p] = tv[p - 1]; tv[p - 1] = a;
                        int   b = ti[p]; ti[p] = ti[p - 1]; ti[p - 1] = b;
                    }
                }
            }
        }
        __syncthreads();
    }

    #pragma unroll
    for (int t = 0; t < NSHORT; ++t) {
        mv[r][sub * 8 + t] = tv[t];
        mi[r][sub * 8 + t] = (unsigned short)ti[t];
    }
    __syncthreads();

    if (tid < 16) {
        int row = tid;
        float fv[NSHORT];
        int   fi[NSHORT];
        #pragma unroll
        for (int t = 0; t < NSHORT; ++t) { fv[t] = -1e30f; fi[t] = 0; }
        for (int e = 0; e < 128; ++e) {
            float v = mv[row][e];
            int jj = (int)mi[row][e];
            if (v > fv[NSHORT - 1] || (v == fv[NSHORT - 1] && jj < fi[NSHORT - 1])) {
                fv[NSHORT - 1] = v; fi[NSHORT - 1] = jj;
                #pragma unroll
                for (int p = NSHORT - 1; p > 0; --p) {
                    if (fv[p] > fv[p - 1] || (fv[p] == fv[p - 1] && fi[p] < fi[p - 1])) {
                        float a = fv[p]; fv[p] = fv[p - 1]; fv[p - 1] = a;
                        int   b = fi[p]; fi[p] = fi[p - 1]; fi[p - 1] = b;
                    }
                }
            }
        }
        int ig = i0 + row;
        #pragma unroll
        for (int t = 0; t < NSHORT; ++t)
            g_short[((size_t)ig * 8 + c) * NSHORT + t] = fi[t];
    }
}

// ---------------------------------------------------------------- refine -----
// fp64 exact terms + fp32 tensor-boundary emulation of the reference dist,
// tie-break by lower index (jax.lax.top_k).
__global__ void __launch_bounds__(256) refine_kernel(
    const float* __restrict__ flat, const float* __restrict__ keys,
    const float* __restrict__ counter, float* __restrict__ out)
{
    int gw = (blockIdx.x * 256 + threadIdx.x) >> 5;   // row = i*8 + c
    int lane = threadIdx.x & 31;
    if (gw >= BB * CB) return;
    int i = gw >> 3, c = gw & 7;

    const float* frow = flat + ((size_t)c * BB + i) * 256;
    double f[8];
    double fn = 0.0;
    #pragma unroll
    for (int k = 0; k < 8; k++) {
        f[k] = (double)frow[lane + 32 * k];
        fn += f[k] * f[k];
    }
    fn = warp_sum_d(fn);

    float sv[NSHORT];
    int   si[NSHORT];
    float A32 = (float)fn;
    #pragma unroll
    for (int t = 0; t < NSHORT; ++t) {
        int idx = g_short[(size_t)gw * NSHORT + t];
        si[t] = idx;
        const float* krow = keys + ((size_t)c * PP + idx) * 256;
        double dot = 0.0, kn = 0.0;
        #pragma unroll
        for (int k = 0; k < 8; k++) {
            double kd = (double)krow[lane + 32 * k];
            dot += f[k] * kd;
            kn  += kd * kd;
        }
        dot = warp_sum_d(dot);
        kn  = warp_sum_d(kn);
        float B32 = 2.0f * (float)dot;
        float C32 = (float)kn;
        float t1  = __fadd_rn(A32, -B32);
        float t2  = __fadd_rn(t1, C32);
        sv[t] = -t2;
    }

    if (lane == 0) {
        #pragma unroll
        for (int a = 0; a < TK; ++a) {
            int best = a;
            #pragma unroll
            for (int b2 = a + 1; b2 < NSHORT; ++b2) {
                if (sv[b2] > sv[best] || (sv[b2] == sv[best] && si[b2] < si[best]))
                    best = b2;
            }
            float vtmp = sv[a]; sv[a] = sv[best]; sv[best] = vtmp;
            int   itmp = si[a]; si[a] = si[best]; si[best] = itmp;
            size_t o = ((size_t)i * 8 + c) * 4 + a;
            out[OFF_IND + o]  = (float)si[a];
            out[OFF_DIST + o] = sv[a];
            out[OFF_CNT + o]  = counter[c * PP + si[a]];
            g_idx[o] = si[a];
        }
    }
}

// ---------------------------------------------------------------- Kernel C ---
__global__ void __launch_bounds__(256) gather_kernel(
    const float* __restrict__ keys, const float* __restrict__ values,
    float* __restrict__ out)
{
    int gw = (blockIdx.x * 256 + threadIdx.x) >> 5;
    int lane = threadIdx.x & 31;
    int c = (gw >> 2) & 7;
    int idx = g_idx[gw];
    const float4* ks = (const float4*)(keys   + ((size_t)c * PP + idx) * 256);
    const float4* vs = (const float4*)(values + ((size_t)c * PP + idx) * 256);
    float4* oqk = (float4*)(out + OFF_QK) + (size_t)gw * 64;
    float4* oqv = (float4*)(out + OFF_QV) + (size_t)gw * 64;
    oqv[lane]      = vs[lane];
    oqv[lane + 32] = vs[lane + 32];
    oqk[lane]      = ks[lane];
    oqk[lane + 32] = ks[lane + 32];
}

// -----------------------------------------------------------------------------
extern "C" void kernel_launch(void* const* d_in, const int* in_sizes, int n_in,
                              void* d_out, int out_size) {
    const float* x       = (const float*)d_in[0];
    const float* keys    = (const float*)d_in[1];
    const float* values  = (const float*)d_in[2];
    const float* counter = (const float*)d_in[3];
    const float* ln1_g   = (const float*)d_in[4];
    const float* ln1_b   = (const float*)d_in[5];
    const float* w_in    = (const float*)d_in[6];
    const float* b_in    = (const float*)d_in[7];
    const float* w_out   = (const float*)d_in[8];
    const float* b_out   = (const float*)d_in[9];
    const float* ln2_g   = (const float*)d_in[10];
    const float* ln2_b   = (const float*)d_in[11];
    const float* fw1     = (const float*)d_in[12];
    const float* fb1     = (const float*)d_in[13];
    const float* fw2     = (const float*)d_in[14];
    const float* fb2     = (const float*)d_in[15];
    const float* dw      = (const float*)d_in[16];
    const float* db      = (const float*)d_in[17];
    float* out = (float*)d_out;

    float4* wt_in;  cudaGetSymbolAddress((void**)&wt_in,  g_wT_in);
    float4* wt_out; cudaGetSymbolAddress((void**)&wt_out, g_wT_out);
    float4* wt_f1;  cudaGetSymbolAddress((void**)&wt_f1,  g_wT_f1);
    float4* wt_f2;  cudaGetSymbolAddress((void**)&wt_f2,  g_wT_f2);
    float4* wt_dec; cudaGetSymbolAddress((void**)&wt_dec, g_wT_dec);

    transW_kernel<<<(64 * 768 + 255) / 256, 256>>>(w_in,  wt_in,  768);
    transW_kernel<<<(64 * 256 + 255) / 256, 256>>>(w_out, wt_out, 256);
    transW_kernel<<<(64 * 256 + 255) / 256, 256>>>(fw1,   wt_f1,  256);
    transW_kernel<<<(64 * 256 + 255) / 256, 256>>>(fw2,   wt_f2,  256);
    transW_kernel<<<(64 * 256 + 255) / 256, 256>>>(dw,    wt_dec, 256);
    transK_kernel<<<CB * 64 * PP / 256, 256>>>(keys);
    knorm_kernel<<<2048, 256>>>(keys);

    enc_kernel<<<BB, 256>>>(x, ln1_g, ln1_b, b_in, b_out,
                            ln2_g, ln2_b, fb1, fb2, db, out + OFF_FLAT);
    dist_kernel<<<dim3(BB / 16, CB), 256>>>(out + OFF_FLAT);
    refine_kernel<<<BB * CB / 8, 256>>>(out + OFF_FLAT, keys, counter, out);
    gather_kernel<<<32768, 256>>>(keys, values, out);
}